// round 1
// baseline (speedup 1.0000x reference)
#include <cuda_runtime.h>

// SeqSelfAttention (Bahdanau additive, windowed) — GB300 sm_103a
// B=4, L=1024, D=128, U=32, WIDTH=64, EPS=1e-7
//
// Key algebra: softmax shift by window-max instead of full-row-max changes the
// result only through the +1e-7 denominator term by a factor exp(Mw-Mfull);
// with |e|<=sum|Wa|~4.5 the induced rel err is <=~1e-6. ba cancels exactly.
// => only the 64-wide window is ever evaluated: 8.4M tanh instead of 134M.

#define LSEQ 1024
#define BB   4
#define DD   128
#define UU   32
#define TI   8
#define CW   72   // TI + 64 : union of windows for TI consecutive queries
#define NROWS (BB*LSEQ)

// scratch (allocation-free rule -> __device__ globals)
__device__ float g_q [NROWS*UU];
__device__ float g_kb[NROWS*UU];

__device__ __forceinline__ float fast_tanh(float x){
    float y;
    asm("tanh.approx.f32 %0, %1;" : "=f"(y) : "f"(x));
    return y;
}

// ---------------------------------------------------------------------------
// Kernel 1: q = x @ Wt ; kb = x @ Wx + bh      (x:[4096,128], W:[128,32])
// 128 blocks x 256 threads, 32 rows per block.
// ---------------------------------------------------------------------------
__global__ __launch_bounds__(256) void qk_kernel(
        const float* __restrict__ x,
        const float* __restrict__ Wt,
        const float* __restrict__ Wx,
        const float* __restrict__ bh)
{
    __shared__ float xs [32*128];   // 16 KB
    __shared__ float wts[128*32];   // 16 KB
    __shared__ float wxs[128*32];   // 16 KB
    const int t    = threadIdx.x;
    const int row0 = blockIdx.x * 32;

    {   // stage tiles (all fully coalesced float4 copies)
        const float4* xg = (const float4*)(x + row0*DD);
        float4* xs4 = (float4*)xs;
        #pragma unroll
        for (int i = t; i < 1024; i += 256) xs4[i] = xg[i];
        const float4* wtg = (const float4*)Wt; float4* wt4 = (float4*)wts;
        const float4* wxg = (const float4*)Wx; float4* wx4 = (float4*)wxs;
        #pragma unroll
        for (int i = t; i < 1024; i += 256){ wt4[i] = wtg[i]; wx4[i] = wxg[i]; }
    }
    __syncthreads();

    const int u  = t & 31;        // lane = unit  -> conflict-free W reads
    const int rg = t >> 5;        // warp-uniform -> broadcast x reads
    float aq0=0,aq1=0,aq2=0,aq3=0, ak0=0,ak1=0,ak2=0,ak3=0;
    const float* xr = xs + rg*4*DD;
    #pragma unroll 4
    for (int d = 0; d < DD; d++){
        const float wt = wts[d*32+u];
        const float wx = wxs[d*32+u];
        const float x0 = xr[d], x1 = xr[DD+d], x2 = xr[2*DD+d], x3 = xr[3*DD+d];
        aq0 += x0*wt; aq1 += x1*wt; aq2 += x2*wt; aq3 += x3*wt;
        ak0 += x0*wx; ak1 += x1*wx; ak2 += x2*wx; ak3 += x3*wx;
    }
    const float bhv = bh[u];
    const int r = row0 + rg*4;
    g_q [(r+0)*UU+u] = aq0;      g_q [(r+1)*UU+u] = aq1;
    g_q [(r+2)*UU+u] = aq2;      g_q [(r+3)*UU+u] = aq3;
    g_kb[(r+0)*UU+u] = ak0+bhv;  g_kb[(r+1)*UU+u] = ak1+bhv;
    g_kb[(r+2)*UU+u] = ak2+bhv;  g_kb[(r+3)*UU+u] = ak3+bhv;
}

// ---------------------------------------------------------------------------
// Kernel 2: windowed additive attention. grid (L/TI, B), 128 threads.
// smem: xs[72][128] | kbs[72][33] | qs[8][32] | was[32] | A[72][8]
// vbuf (phase-C partials) overlays kbs (dead after phase A).
// ---------------------------------------------------------------------------
#define OFF_XS   0
#define OFF_KBS  (CW*DD)                 // 9216
#define OFF_QS   (OFF_KBS + CW*33)       // 11592
#define OFF_WAS  (OFF_QS + TI*UU)        // 11848
#define OFF_A    (OFF_WAS + UU)          // 11880  (byte 47520, 16B aligned)
#define SMEM_FLOATS (OFF_A + CW*TI)      // 12456 floats = 49824 B

extern __shared__ float smem[];

__global__ __launch_bounds__(128) void attn_kernel(
        const float* __restrict__ x,
        const float* __restrict__ Wa,
        float* __restrict__ out)
{
    float* xs   = smem + OFF_XS;
    float* kbs  = smem + OFF_KBS;
    float* qs   = smem + OFF_QS;
    float* was  = smem + OFF_WAS;
    float* Aw   = smem + OFF_A;
    float* vbuf = kbs;                    // overlay: [2][8][128]

    const int t    = threadIdx.x;
    const int i0   = blockIdx.x * TI;
    const int base = blockIdx.y * LSEQ;   // row base for this batch

    // ---- stage x window [72][128] (float4) and kb window [72][33] ----
    {
        float4* xs4 = (float4*)xs;
        const float4* xg4 = (const float4*)x;
        #pragma unroll
        for (int i = 0; i < 18; i++){
            const int idx = t + i*128;            // float4 idx into [72][32]
            const int c = idx >> 5, dq = idx & 31;
            const int j = i0 - 32 + c;
            float4 v = make_float4(0.f,0.f,0.f,0.f);
            if (j >= 0 && j < LSEQ) v = xg4[(base + j)*32 + dq];
            xs4[c*32 + dq] = v;
        }
        #pragma unroll
        for (int i = 0; i < 18; i++){
            const int idx = t + i*128;
            const int c = idx >> 5, u = idx & 31;
            const int j = i0 - 32 + c;
            kbs[c*33 + u] = (j >= 0 && j < LSEQ) ? g_kb[(base + j)*UU + u] : 0.f;
        }
        qs[t]     = g_q[(base + i0)*UU + t];
        qs[t+128] = g_q[(base + i0)*UU + t + 128];
        if (t < 32) was[t] = Wa[t];
        Aw[t] = 0.f; Aw[t+128] = 0.f; Aw[t+256] = 0.f; Aw[t+384] = 0.f;
        if (t < 64) Aw[t+512] = 0.f;
    }
    __syncthreads();

    // ---- phase A: e[ii][jj] = sum_u Wa_u * tanh(q[ii][u] + kb[c][u]), c=ii+jj
    {
        const int ii   = t >> 4;
        const int jj4  = (t & 15) << 2;
        const int cb   = ii + jj4;
        float e0=0.f, e1=0.f, e2=0.f, e3=0.f;
        const float* qrow = qs + ii*UU;
        #pragma unroll
        for (int u = 0; u < UU; u++){
            const float qv = qrow[u];
            const float wa = was[u];
            const float* kp = kbs + cb*33 + u;
            e0 += wa * fast_tanh(qv + kp[0]);
            e1 += wa * fast_tanh(qv + kp[33]);
            e2 += wa * fast_tanh(qv + kp[66]);
            e3 += wa * fast_tanh(qv + kp[99]);
        }
        float ev[4] = {e0, e1, e2, e3};
        #pragma unroll
        for (int k = 0; k < 4; k++){
            const int c = cb + k;
            const int j = i0 - 32 + c;
            float e = ev[k];
            if (j < 0 || j >= LSEQ) e = -1e30f;   // outside sequence
            Aw[c*TI + ii] = e;
        }
    }
    __syncthreads();

    // ---- phase B: per-row window softmax (warp handles 2 rows) ----
    {
        const int w = t >> 5, l = t & 31;
        #pragma unroll
        for (int rr = 0; rr < 2; rr++){
            const int ii = w*2 + rr;
            const int c0 = ii + l, c1 = c0 + 32;
            const float e0 = Aw[c0*TI + ii];
            const float e1 = Aw[c1*TI + ii];
            float m = fmaxf(e0, e1);
            #pragma unroll
            for (int o = 16; o; o >>= 1) m = fmaxf(m, __shfl_xor_sync(0xffffffffu, m, o));
            const float w0 = __expf(e0 - m);       // -1e30 rows -> 0
            const float w1 = __expf(e1 - m);
            float s = w0 + w1;
            #pragma unroll
            for (int o = 16; o; o >>= 1) s += __shfl_xor_sync(0xffffffffu, s, o);
            const float inv = 1.f / (s + 1e-7f);
            Aw[c0*TI + ii] = w0 * inv;
            Aw[c1*TI + ii] = w1 * inv;
        }
    }
    __syncthreads();

    // ---- phase C: v[ii][:] = sum_c A[c][ii] * x[c][:]  (split c-range) ----
    {
        const int w = t >> 5, l = t & 31;
        const int h   = w >> 1;          // c-range half
        const int iis = (w & 1) * 4;     // ii group 0-3 / 4-7
        float4 acc[4];
        #pragma unroll
        for (int k = 0; k < 4; k++) acc[k] = make_float4(0.f,0.f,0.f,0.f);
        const float4* A4  = (const float4*)Aw;
        const float4* xs4 = (const float4*)xs;
        const int cbeg = h * 36, cend = cbeg + 36;
        for (int c = cbeg; c < cend; c++){
            const float4 a4 = A4[c*2 + (w & 1)];        // broadcast
            const float4 xv = xs4[c*32 + l];            // conflict-free LDS.128
            const float av[4] = {a4.x, a4.y, a4.z, a4.w};
            #pragma unroll
            for (int k = 0; k < 4; k++){
                acc[k].x += av[k]*xv.x;  acc[k].y += av[k]*xv.y;
                acc[k].z += av[k]*xv.z;  acc[k].w += av[k]*xv.w;
            }
        }
        float4* vb4 = (float4*)vbuf;
        #pragma unroll
        for (int k = 0; k < 4; k++)
            vb4[(h*TI + iis + k)*32 + l] = acc[k];
    }
    __syncthreads();

    // ---- merge halves, write out ----
    {
        const float4* vb4 = (const float4*)vbuf;
        float4* out4 = (float4*)out;
        #pragma unroll
        for (int i = 0; i < 2; i++){
            const int idx = t + i*128;                // 0..255
            const int ii = idx >> 5, dq = idx & 31;
            const float4 p = vb4[ii*32 + dq];
            const float4 q2 = vb4[(TI+ii)*32 + dq];
            float4 r;
            r.x = p.x+q2.x; r.y = p.y+q2.y; r.z = p.z+q2.z; r.w = p.w+q2.w;
            out4[(base + i0 + ii)*32 + dq] = r;
        }
    }
}

// ---------------------------------------------------------------------------
extern "C" void kernel_launch(void* const* d_in, const int* in_sizes, int n_in,
                              void* d_out, int out_size)
{
    const float* x  = (const float*)d_in[0];
    const float* Wt = (const float*)d_in[1];
    const float* Wx = (const float*)d_in[2];
    const float* bh = (const float*)d_in[3];
    const float* Wa = (const float*)d_in[4];
    // d_in[5] = ba : cancels exactly in the shifted softmax -> unused
    float* out = (float*)d_out;

    qk_kernel<<<NROWS/32, 256>>>(x, Wt, Wx, bh);

    cudaFuncSetAttribute(attn_kernel,
                         cudaFuncAttributeMaxDynamicSharedMemorySize,
                         SMEM_FLOATS*4 + 256);
    dim3 grid(LSEQ/TI, BB);
    attn_kernel<<<grid, 128, SMEM_FLOATS*4>>>(x, Wa, out);
}